// round 2
// baseline (speedup 1.0000x reference)
#include <cuda_runtime.h>
#include <cuda_bf16.h>

// ---------------------------------------------------------------------------
// KipfAndWellingConv: out = segment_sum(w_e * (x @ F)[src_e], dst_e)
//   x:       [N=100000, 128] f32
//   filters: [128, 128]      f32
//   edge_src:[E=3.2M] int32 (JAX canonicalizes int64->int32), random
//   edge_dst:[E] int32, SORTED ascending
//   edge_weight: [E] f32
//   out:     [N, 128] f32
// ---------------------------------------------------------------------------

#define NF 128               // features == filters
#define GEMM_BM 64
#define EPW 256              // edges per warp in aggregation

// scratch for XF = x @ filters  (100000 * 128 floats = 51.2 MB)
__device__ float g_XF[100000 * NF];

// ---------------------------------------------------------------------------
__global__ void zero_kernel(float4* __restrict__ out, int n4)
{
    int i = blockIdx.x * blockDim.x + threadIdx.x;
    if (i < n4) out[i] = make_float4(0.f, 0.f, 0.f, 0.f);
}

// ---------------------------------------------------------------------------
// GEMM: XF[M,128] = X[M,128] @ F[128,128]
// Block: 256 threads, BM=64 rows. K tiled by 32.
// Thread (rg, cg): rows rg*4..+3, cols cg*8..+7 (4x8 register tile).
__global__ __launch_bounds__(256)
void gemm128(const float* __restrict__ X, const float* __restrict__ F, int M)
{
    __shared__ float xs[GEMM_BM][36];   // 32 k + pad
    __shared__ float fs[32][NF];

    const int tid  = threadIdx.x;
    const int row0 = blockIdx.x * GEMM_BM;
    const int rg   = tid >> 4;   // 0..15
    const int cg   = tid & 15;   // 0..15

    float acc[4][8];
#pragma unroll
    for (int i = 0; i < 4; ++i)
#pragma unroll
        for (int j = 0; j < 8; ++j) acc[i][j] = 0.f;

    for (int kt = 0; kt < NF / 32; ++kt) {
        // x tile: 64 rows x 32 k = 512 float4, 2 per thread
#pragma unroll
        for (int p = 0; p < 2; ++p) {
            int i4 = tid + p * 256;
            int r  = i4 >> 3;
            int c  = (i4 & 7) * 4;
            float4 v = make_float4(0.f, 0.f, 0.f, 0.f);
            int grow = row0 + r;
            if (grow < M)
                v = *(const float4*)(X + (size_t)grow * NF + kt * 32 + c);
            *(float4*)&xs[r][c] = v;
        }
        // filter tile: 32 rows x 128 = 1024 float4, 4 per thread
#pragma unroll
        for (int p = 0; p < 4; ++p) {
            int i4 = tid + p * 256;
            int r  = i4 >> 5;
            int c  = (i4 & 31) * 4;
            float4 v = *(const float4*)(F + (size_t)(kt * 32 + r) * NF + c);
            *(float4*)&fs[r][c] = v;
        }
        __syncthreads();

#pragma unroll
        for (int k = 0; k < 32; ++k) {
            float a0 = xs[rg * 4 + 0][k];
            float a1 = xs[rg * 4 + 1][k];
            float a2 = xs[rg * 4 + 2][k];
            float a3 = xs[rg * 4 + 3][k];
            float4 b0 = *(float4*)&fs[k][cg * 8];
            float4 b1 = *(float4*)&fs[k][cg * 8 + 4];
            acc[0][0] += a0 * b0.x; acc[0][1] += a0 * b0.y;
            acc[0][2] += a0 * b0.z; acc[0][3] += a0 * b0.w;
            acc[0][4] += a0 * b1.x; acc[0][5] += a0 * b1.y;
            acc[0][6] += a0 * b1.z; acc[0][7] += a0 * b1.w;
            acc[1][0] += a1 * b0.x; acc[1][1] += a1 * b0.y;
            acc[1][2] += a1 * b0.z; acc[1][3] += a1 * b0.w;
            acc[1][4] += a1 * b1.x; acc[1][5] += a1 * b1.y;
            acc[1][6] += a1 * b1.z; acc[1][7] += a1 * b1.w;
            acc[2][0] += a2 * b0.x; acc[2][1] += a2 * b0.y;
            acc[2][2] += a2 * b0.z; acc[2][3] += a2 * b0.w;
            acc[2][4] += a2 * b1.x; acc[2][5] += a2 * b1.y;
            acc[2][6] += a2 * b1.z; acc[2][7] += a2 * b1.w;
            acc[3][0] += a3 * b0.x; acc[3][1] += a3 * b0.y;
            acc[3][2] += a3 * b0.z; acc[3][3] += a3 * b0.w;
            acc[3][4] += a3 * b1.x; acc[3][5] += a3 * b1.y;
            acc[3][6] += a3 * b1.z; acc[3][7] += a3 * b1.w;
        }
        __syncthreads();
    }

#pragma unroll
    for (int i = 0; i < 4; ++i) {
        int grow = row0 + rg * 4 + i;
        if (grow < M) {
            float* o = g_XF + (size_t)grow * NF + cg * 8;
            *(float4*)(o)     = make_float4(acc[i][0], acc[i][1], acc[i][2], acc[i][3]);
            *(float4*)(o + 4) = make_float4(acc[i][4], acc[i][5], acc[i][6], acc[i][7]);
        }
    }
}

// ---------------------------------------------------------------------------
// Aggregation: one warp per EPW consecutive edges; dst sorted, register
// accumulate per segment, atomicAdd flush on dst change / chunk end.
// Lane l owns features [4l, 4l+4). 1-deep software prefetch.
__global__ __launch_bounds__(256)
void agg_kernel(const int* __restrict__ src,
                const int* __restrict__ dst,
                const float* __restrict__ w,
                float* __restrict__ out, int E)
{
    const int gw   = (blockIdx.x * blockDim.x + threadIdx.x) >> 5;
    const int lane = threadIdx.x & 31;

    long long base = (long long)gw * EPW;
    if (base >= E) return;
    long long end = base + EPW;
    if (end > E) end = E;

    const float4* __restrict__ XF4 = (const float4*)g_XF;

    float4 acc = make_float4(0.f, 0.f, 0.f, 0.f);
    int cur = dst[base];

    // prefetch edge 0
    int    d_n = cur;
    float  w_n = w[base];
    float4 v_n = XF4[(size_t)src[base] * (NF / 4) + lane];

    for (long long e = base; e < end; ++e) {
        const float4 v  = v_n;
        const float  wt = w_n;
        const int    d  = d_n;

        if (e + 1 < end) {           // prefetch next edge
            int s2 = src[e + 1];
            d_n = dst[e + 1];
            w_n = w[e + 1];
            v_n = XF4[(size_t)s2 * (NF / 4) + lane];
        }

        if (d != cur) {              // flush finished segment
            float* o = out + (size_t)cur * NF + lane * 4;
            atomicAdd(o + 0, acc.x);
            atomicAdd(o + 1, acc.y);
            atomicAdd(o + 2, acc.z);
            atomicAdd(o + 3, acc.w);
            acc = make_float4(0.f, 0.f, 0.f, 0.f);
            cur = d;
        }
        acc.x += wt * v.x;
        acc.y += wt * v.y;
        acc.z += wt * v.z;
        acc.w += wt * v.w;
    }
    // final flush
    float* o = out + (size_t)cur * NF + lane * 4;
    atomicAdd(o + 0, acc.x);
    atomicAdd(o + 1, acc.y);
    atomicAdd(o + 2, acc.z);
    atomicAdd(o + 3, acc.w);
}

// ---------------------------------------------------------------------------
extern "C" void kernel_launch(void* const* d_in, const int* in_sizes, int n_in,
                              void* d_out, int out_size)
{
    const float* x    = (const float*)d_in[0];
    const float* f    = (const float*)d_in[1];
    const int*   esrc = (const int*)d_in[2];
    const int*   edst = (const int*)d_in[3];
    const float* ew   = (const float*)d_in[4];
    float*       out  = (float*)d_out;

    const int M = in_sizes[0] / NF;       // 100000
    const int E = in_sizes[2];            // 3200000

    // 1) zero output (poisoned by harness)
    int n4 = out_size / 4;
    zero_kernel<<<(n4 + 255) / 256, 256>>>((float4*)out, n4);

    // 2) XF = x @ filters
    gemm128<<<(M + GEMM_BM - 1) / GEMM_BM, 256>>>(x, f, M);

    // 3) segment-sum over edges
    int warps  = (E + EPW - 1) / EPW;
    int blocks = (warps * 32 + 255) / 256;
    agg_kernel<<<blocks, 256>>>(esrc, edst, ew, out, E);
}

// round 3
// speedup vs baseline: 1.4547x; 1.4547x over previous
#include <cuda_runtime.h>
#include <cuda_bf16.h>
#include <cstdint>

// ---------------------------------------------------------------------------
// KipfAndWellingConv: out = segment_sum(w_e * (x @ F)[src_e], dst_e)
//   x [100000,128] f32, filters [128,128] f32,
//   edge_src/edge_dst [3.2M] int32 (dst sorted), edge_weight f32
//   out [100000,128] f32
// R3: GEMM on tensor cores (tf32 mma.sync m16n8k8), agg unchanged.
// ---------------------------------------------------------------------------

#define NF 128
#define EPW 256              // edges per warp in aggregation

__device__ float g_XF[100000 * NF];   // XF scratch (51.2 MB)

// ---------------------------------------------------------------------------
__global__ void zero_kernel(float4* __restrict__ out, int n4)
{
    int i = blockIdx.x * blockDim.x + threadIdx.x;
    if (i < n4) out[i] = make_float4(0.f, 0.f, 0.f, 0.f);
}

// ---------------------------------------------------------------------------
__device__ __forceinline__ float to_tf32(float x)
{
    float r;
    asm("cvt.rna.tf32.f32 %0, %1;" : "=f"(r) : "f"(x));
    return r;
}

__device__ __forceinline__ void mma_tf32(float* d, const uint32_t* a, const uint32_t* b)
{
    asm volatile(
        "mma.sync.aligned.m16n8k8.row.col.f32.tf32.tf32.f32 "
        "{%0,%1,%2,%3}, {%4,%5,%6,%7}, {%8,%9}, {%0,%1,%2,%3};\n"
        : "+f"(d[0]), "+f"(d[1]), "+f"(d[2]), "+f"(d[3])
        : "r"(a[0]), "r"(a[1]), "r"(a[2]), "r"(a[3]), "r"(b[0]), "r"(b[1]));
}

// GEMM: XF[M,128] = X[M,128] @ F[128,128] using tf32 tensor cores.
// Block: 256 thr / 8 warps. Block tile 64x128, warp tile 32x32 (2x4 m16n8k8).
__global__ __launch_bounds__(256)
void gemm_tf32(const float* __restrict__ X, const float* __restrict__ F, int M)
{
    __shared__ float As[64][36];    // 64x32 tile, pad->36 (conflict-free frags)
    __shared__ float Bs[32][136];   // 32x128 tile, pad->136 (8t+g pattern)

    const int tid  = threadIdx.x;
    const int row0 = blockIdx.x * 64;
    const int wid  = tid >> 5;
    const int lane = tid & 31;
    const int g    = lane >> 2;     // group 0..7
    const int t    = lane & 3;      // thread-in-group 0..3
    const int wm0  = (wid >> 2) * 32;   // 0 / 32
    const int wn0  = (wid & 3) * 32;    // 0 / 32 / 64 / 96

    float d[2][4][4];
#pragma unroll
    for (int i = 0; i < 2; ++i)
#pragma unroll
        for (int j = 0; j < 4; ++j)
#pragma unroll
            for (int k = 0; k < 4; ++k) d[i][j][k] = 0.f;

    for (int kt = 0; kt < 4; ++kt) {
        // A tile: 64 rows x 32 k = 512 float4, 2 per thread
#pragma unroll
        for (int p = 0; p < 2; ++p) {
            int i4 = tid + p * 256;
            int r  = i4 >> 3;
            int c  = (i4 & 7) * 4;
            float4 v = make_float4(0.f, 0.f, 0.f, 0.f);
            int grow = row0 + r;
            if (grow < M)
                v = *(const float4*)(X + (size_t)grow * NF + kt * 32 + c);
            v.x = to_tf32(v.x); v.y = to_tf32(v.y);
            v.z = to_tf32(v.z); v.w = to_tf32(v.w);
            *(float4*)&As[r][c] = v;
        }
        // B tile: 32 k x 128 n = 1024 float4, 4 per thread
#pragma unroll
        for (int p = 0; p < 4; ++p) {
            int i4 = tid + p * 256;
            int r  = i4 >> 5;
            int c  = (i4 & 31) * 4;
            float4 v = *(const float4*)(F + (size_t)(kt * 32 + r) * NF + c);
            v.x = to_tf32(v.x); v.y = to_tf32(v.y);
            v.z = to_tf32(v.z); v.w = to_tf32(v.w);
            *(float4*)&Bs[r][c] = v;
        }
        __syncthreads();

#pragma unroll
        for (int k8 = 0; k8 < 4; ++k8) {
            const int kb = k8 * 8;
            uint32_t a[2][4], b[4][2];
#pragma unroll
            for (int im = 0; im < 2; ++im) {
                int rb = wm0 + im * 16 + g;
                a[im][0] = __float_as_uint(As[rb][kb + t]);
                a[im][1] = __float_as_uint(As[rb + 8][kb + t]);
                a[im][2] = __float_as_uint(As[rb][kb + t + 4]);
                a[im][3] = __float_as_uint(As[rb + 8][kb + t + 4]);
            }
#pragma unroll
            for (int jn = 0; jn < 4; ++jn) {
                int cb = wn0 + jn * 8 + g;
                b[jn][0] = __float_as_uint(Bs[kb + t][cb]);
                b[jn][1] = __float_as_uint(Bs[kb + t + 4][cb]);
            }
#pragma unroll
            for (int im = 0; im < 2; ++im)
#pragma unroll
                for (int jn = 0; jn < 4; ++jn)
                    mma_tf32(d[im][jn], a[im], b[jn]);
        }
        __syncthreads();
    }

    // Epilogue: c0/c1 -> row g, cols t*2/t*2+1 ; c2/c3 -> row g+8
#pragma unroll
    for (int im = 0; im < 2; ++im) {
#pragma unroll
        for (int half = 0; half < 2; ++half) {
            int grow = row0 + wm0 + im * 16 + half * 8 + g;
            if (grow < M) {
#pragma unroll
                for (int jn = 0; jn < 4; ++jn) {
                    float2 v = make_float2(d[im][jn][half * 2],
                                           d[im][jn][half * 2 + 1]);
                    *(float2*)(g_XF + (size_t)grow * NF + wn0 + jn * 8 + t * 2) = v;
                }
            }
        }
    }
}

// ---------------------------------------------------------------------------
// Aggregation: warp per EPW consecutive edges; dst sorted, register
// accumulate per segment, atomicAdd flush on dst change / chunk end.
__global__ __launch_bounds__(256)
void agg_kernel(const int* __restrict__ src,
                const int* __restrict__ dst,
                const float* __restrict__ w,
                float* __restrict__ out, int E)
{
    const int gw   = (blockIdx.x * blockDim.x + threadIdx.x) >> 5;
    const int lane = threadIdx.x & 31;

    long long base = (long long)gw * EPW;
    if (base >= E) return;
    long long end = base + EPW;
    if (end > E) end = E;

    const float4* __restrict__ XF4 = (const float4*)g_XF;

    float4 acc = make_float4(0.f, 0.f, 0.f, 0.f);
    int cur = dst[base];

    int    d_n = cur;
    float  w_n = w[base];
    float4 v_n = XF4[(size_t)src[base] * (NF / 4) + lane];

    for (long long e = base; e < end; ++e) {
        const float4 v  = v_n;
        const float  wt = w_n;
        const int    dd = d_n;

        if (e + 1 < end) {
            int s2 = src[e + 1];
            d_n = dst[e + 1];
            w_n = w[e + 1];
            v_n = XF4[(size_t)s2 * (NF / 4) + lane];
        }

        if (dd != cur) {
            float* o = out + (size_t)cur * NF + lane * 4;
            atomicAdd(o + 0, acc.x);
            atomicAdd(o + 1, acc.y);
            atomicAdd(o + 2, acc.z);
            atomicAdd(o + 3, acc.w);
            acc = make_float4(0.f, 0.f, 0.f, 0.f);
            cur = dd;
        }
        acc.x += wt * v.x;
        acc.y += wt * v.y;
        acc.z += wt * v.z;
        acc.w += wt * v.w;
    }
    float* o = out + (size_t)cur * NF + lane * 4;
    atomicAdd(o + 0, acc.x);
    atomicAdd(o + 1, acc.y);
    atomicAdd(o + 2, acc.z);
    atomicAdd(o + 3, acc.w);
}

// ---------------------------------------------------------------------------
extern "C" void kernel_launch(void* const* d_in, const int* in_sizes, int n_in,
                              void* d_out, int out_size)
{
    const float* x    = (const float*)d_in[0];
    const float* f    = (const float*)d_in[1];
    const int*   esrc = (const int*)d_in[2];
    const int*   edst = (const int*)d_in[3];
    const float* ew   = (const float*)d_in[4];
    float*       out  = (float*)d_out;

    const int M = in_sizes[0] / NF;   // 100000
    const int E = in_sizes[2];        // 3200000

    int n4 = out_size / 4;
    zero_kernel<<<(n4 + 255) / 256, 256>>>((float4*)out, n4);

    gemm_tf32<<<(M + 63) / 64, 256>>>(x, f, M);

    int warps  = (E + EPW - 1) / EPW;
    int blocks = (warps * 32 + 255) / 256;
    agg_kernel<<<blocks, 256>>>(esrc, edst, ew, out, E);
}